// round 9
// baseline (speedup 1.0000x reference)
#include <cuda_runtime.h>
#include <cstdint>

// Problem constants
#define BATCH 8
#define SEQ   4096
#define DM    64
#define DS    16
#define ROWS  (BATCH*SEQ)     // 32768 timesteps total
#define CH    64              // chunk length for parallel scan
#define NCHUNK (ROWS/CH)      // 512
#define CPB   (SEQ/CH)        // 64 chunks per batch

#define XPAD 68               // x tile row stride (floats)
#define WPAD 136              // weight tile row stride (floats) — conflict-free
#define HPAD 17               // hs tile row stride

// ---------------------------------------------------------------------------
// Device scratch
// ---------------------------------------------------------------------------
__device__ float g_A  [ROWS*256];   // A_t, then in-place chunk prefixes M_t
__device__ float g_Bx [ROWS*DS];    // Bx_t, then in-place prefixes v_t
__device__ float g_M  [NCHUNK*256];
__device__ float g_v  [NCHUNK*DS];
__device__ float g_h0 [NCHUNK*DS];
__device__ float g_WAt[64*256];     // tf32-rounded weights
__device__ float g_WBt[64*1024];
__device__ float g_WCt[64*1024];

extern __shared__ float smem[];

// ---------------------------------------------------------------------------
// helpers
// ---------------------------------------------------------------------------
__device__ __forceinline__ float tf32r(float v) {
    uint32_t o;
    asm("cvt.rna.tf32.f32 %0, %1;" : "=r"(o) : "f"(v));
    return __uint_as_float(o);
}

__device__ __forceinline__ void mma_tf32(float c[4],
                                         float a0, float a1, float a2, float a3,
                                         float b0, float b1)
{
    asm volatile(
        "mma.sync.aligned.m16n8k8.row.col.f32.tf32.tf32.f32 "
        "{%0,%1,%2,%3}, {%4,%5,%6,%7}, {%8,%9}, {%0,%1,%2,%3};\n"
        : "+f"(c[0]), "+f"(c[1]), "+f"(c[2]), "+f"(c[3])
        : "r"(__float_as_uint(a0)), "r"(__float_as_uint(a1)),
          "r"(__float_as_uint(a2)), "r"(__float_as_uint(a3)),
          "r"(__float_as_uint(b0)), "r"(__float_as_uint(b1)));
}

__device__ __forceinline__ void cp16(float* dst_smem, const float* src) {
    uint32_t d = (uint32_t)__cvta_generic_to_shared(dst_smem);
    asm volatile("cp.async.cg.shared.global [%0], [%1], 16;\n"
                 :: "r"(d), "l"(src));
}
__device__ __forceinline__ void cp_commit() {
    asm volatile("cp.async.commit_group;\n");
}
__device__ __forceinline__ void cp_wait_all() {
    asm volatile("cp.async.wait_group 0;\n");
}

// ---------------------------------------------------------------------------
// K0: one-time tf32 rounding of all weights.
// ---------------------------------------------------------------------------
__global__ __launch_bounds__(256, 4)
void k0_round(const float* __restrict__ WA, const float* __restrict__ WB,
              const float* __restrict__ WC)
{
    int i = blockIdx.x * 256 + threadIdx.x;       // float4 index, 36864 total
    const float* src; float* dst; int off;
    if (i < 4096)       { src = WA; dst = g_WAt; off = i; }
    else if (i < 20480) { src = WB; dst = g_WBt; off = i - 4096; }
    else                { src = WC; dst = g_WCt; off = i - 20480; }
    float4 v = ((const float4*)src)[off];
    ((float4*)dst)[off] = make_float4(tf32r(v.x), tf32r(v.y),
                                      tf32r(v.z), tf32r(v.w));
}

// ---------------------------------------------------------------------------
// K1 (tf32, cp.async pipelined): A = x@W_A + b_A -> g_A ; Bx -> g_Bx.
// Weight chunks (128 cols) stream through a 2-deep cp.async ring.
// ---------------------------------------------------------------------------
__global__ __launch_bounds__(256, 2)
void k1_proj(const float* __restrict__ x,
             const float* __restrict__ bA, const float* __restrict__ bB)
{
    float* xs_f = smem;               // 4352: raw f32 x tile
    float* Wf0  = smem + 4352;        // 8704: weight ring buffer 0
    float* Wf1  = smem + 13056;       // 8704: ring buffer 1
    float* bsh  = smem + 21760;       // 1280: biases (bA then bB)
    float* Bxs  = smem + 23040;       // 1024: Bx tile [64][16]

    const int tid  = threadIdx.x;
    const int row0 = blockIdx.x * 64;

    // stage chunk 0 (W_A cols 0..127) immediately
    {
        float* dst = Wf0;
#pragma unroll
        for (int s = 0; s < 8; s++) {
            int i = tid + s * 256, r = i >> 5, q = i & 31;
            cp16(dst + r * WPAD + q * 4, g_WAt + (size_t)r * 256 + q * 4);
        }
        cp_commit();
    }

    for (int i = tid; i < 64 * 16; i += 256) {
        int r = i >> 4, c4 = i & 15;
        ((float4*)(xs_f + r * XPAD))[c4] =
            ((const float4*)(x + (size_t)(row0 + r) * DM))[c4];
    }
    for (int i = tid; i < 256;  i += 256) bsh[i]       = bA[i];
    for (int i = tid; i < 1024; i += 256) bsh[256 + i] = bB[i];
    __syncthreads();

    const int lane = tid & 31;
    const int g    = lane >> 2;
    const int tg   = lane & 3;
    const int wid  = tid >> 5;
    const int wm   = wid >> 1;
    const int wn   = wid & 1;
    const int rA0  = wm * 16 + g;
    const int rA1  = rA0 + 8;

    // A fragments cached in registers (rounded from raw copy)
    float af[8][4];
#pragma unroll
    for (int k = 0; k < 8; k++) {
        af[k][0] = tf32r(xs_f[rA0 * XPAD + k * 8 + tg]);
        af[k][1] = tf32r(xs_f[rA1 * XPAD + k * 8 + tg]);
        af[k][2] = tf32r(xs_f[rA0 * XPAD + k * 8 + tg + 4]);
        af[k][3] = tf32r(xs_f[rA1 * XPAD + k * 8 + tg + 4]);
    }

    for (int c = 0; c < 10; c++) {
        cp_wait_all();          // chunk c landed
        __syncthreads();        // + all warps done with the other buffer

        // prefetch chunk c+1 into the other buffer (overlaps with MMAs below)
        if (c < 9) {
            float* dst = ((c + 1) & 1) ? Wf1 : Wf0;
            const float* src; int ldw, colbase;
            if (c + 1 < 2) { src = g_WAt; ldw = 256;  colbase = (c + 1) * 128; }
            else           { src = g_WBt; ldw = 1024; colbase = (c - 1) * 128; }
#pragma unroll
            for (int s = 0; s < 8; s++) {
                int i = tid + s * 256, r = i >> 5, q = i & 31;
                cp16(dst + r * WPAD + q * 4,
                     src + (size_t)r * ldw + colbase + q * 4);
            }
            cp_commit();
        }

        const float* Wt = (c & 1) ? Wf1 : Wf0;

        float cfr[8][4];
#pragma unroll
        for (int nt = 0; nt < 8; nt++)
#pragma unroll
            for (int j = 0; j < 4; j++) cfr[nt][j] = 0.f;

#pragma unroll
        for (int k = 0; k < 8; k++) {
#pragma unroll
            for (int nt = 0; nt < 8; nt++) {
                float b0 = Wt[(k * 8 + tg)     * WPAD + wn * 64 + nt * 8 + g];
                float b1 = Wt[(k * 8 + tg + 4) * WPAD + wn * 64 + nt * 8 + g];
                mma_tf32(cfr[nt], af[k][0], af[k][1], af[k][2], af[k][3], b0, b1);
            }
        }

        if (c < 2) {
            // A-projection: add bias, store raw A_t (unique writer/element)
#pragma unroll
            for (int nt = 0; nt < 8; nt++) {
                int gcol = c * 128 + wn * 64 + nt * 8 + 2 * tg;
                float b0v = bsh[gcol], b1v = bsh[gcol + 1];
                float2 s0 = make_float2(cfr[nt][0] + b0v, cfr[nt][1] + b1v);
                float2 s1 = make_float2(cfr[nt][2] + b0v, cfr[nt][3] + b1v);
                *(float2*)&g_A[(size_t)(row0 + rA0) * 256 + gcol] = s0;
                *(float2*)&g_A[(size_t)(row0 + rA1) * 256 + gcol] = s1;
            }
        } else {
            // B-projection: contract with raw x over d, reduce over quad
            const int n = (c - 2) * 2 + wn;
            float pg = 0.f, pg8 = 0.f;
#pragma unroll
            for (int nt = 0; nt < 8; nt++) {
                int bcol = (c - 2) * 128 + wn * 64 + nt * 8 + 2 * tg;
                int d    = nt * 8 + 2 * tg;
                float b0v = bsh[256 + bcol], b1v = bsh[256 + bcol + 1];
                pg  += (cfr[nt][0] + b0v) * xs_f[rA0 * XPAD + d]
                     + (cfr[nt][1] + b1v) * xs_f[rA0 * XPAD + d + 1];
                pg8 += (cfr[nt][2] + b0v) * xs_f[rA1 * XPAD + d]
                     + (cfr[nt][3] + b1v) * xs_f[rA1 * XPAD + d + 1];
            }
            pg  += __shfl_xor_sync(0xffffffffu, pg,  1);
            pg  += __shfl_xor_sync(0xffffffffu, pg,  2);
            pg8 += __shfl_xor_sync(0xffffffffu, pg8, 1);
            pg8 += __shfl_xor_sync(0xffffffffu, pg8, 2);
            if (tg == 0) {
                Bxs[rA0 * 16 + n] = pg;
                Bxs[rA1 * 16 + n] = pg8;
            }
        }
    }
    __syncthreads();
    for (int i = tid; i < 64 * DS; i += 256)
        g_Bx[(size_t)row0 * DS + i] = Bxs[i];
}

// ---------------------------------------------------------------------------
// K2: per-chunk prefix scan; overwrites g_A / g_Bx in place, summary to g_M/g_v.
// ---------------------------------------------------------------------------
__global__ __launch_bounds__(256, 1)
void k2_chunk_prefix()
{
    float* As  = smem;            // 16384 floats
    float* Bxs = smem + 16384;    // 1024
    float* Msh = smem + 17408;    // 2 x 272
    float* vsh = smem + 17952;    // 2 x 16

    const int tid   = threadIdx.x;
    const int chunk = blockIdx.x;
    const size_t base = (size_t)chunk * CH;

    for (int i = tid; i < 4096; i += 256)
        ((float4*)As)[i] = ((const float4*)(g_A + base * 256))[i];
    for (int i = tid; i < 256; i += 256)
        ((float4*)Bxs)[i] = ((const float4*)(g_Bx + base * DS))[i];
    __syncthreads();

    const int i = tid >> 4, j = tid & 15;
    Msh[i * 17 + j] = As[i * 16 + j];
    if (j == 0) vsh[i] = Bxs[i];
    __syncthreads();

    for (int t = 1; t < CH; t++) {
        const int cur = t & 1, prev = cur ^ 1;
        const float* Ar = As + t * 256 + i * 16;
        const float* Mp = Msh + prev * 272;
        float s0 = 0.f, s1 = 0.f;
#pragma unroll
        for (int k = 0; k < 16; k += 2) {
            s0 += Ar[k]     * Mp[k * 17 + j];
            s1 += Ar[k + 1] * Mp[(k + 1) * 17 + j];
        }
        float nm = s0 + s1;
        Msh[cur * 272 + i * 17 + j] = nm;
        g_A[(base + t) * 256 + tid] = nm;
        if (j == 0) {
            const float* vp = vsh + prev * 16;
            float nv = Bxs[t * DS + i];
#pragma unroll
            for (int k = 0; k < 16; k++) nv += Ar[k] * vp[k];
            vsh[cur * 16 + i] = nv;
            g_Bx[(base + t) * DS + i] = nv;
        }
        __syncthreads();
    }

    const int f = (CH - 1) & 1;
    g_M[(size_t)chunk * 256 + tid] = Msh[f * 272 + i * 17 + j];
    if (j == 0) g_v[(size_t)chunk * DS + i] = vsh[f * 16 + i];
}

// ---------------------------------------------------------------------------
// K3: sequential prefix over chunk summaries (64 per batch). One block/batch.
// M tile staged with 17-float row pitch -> banks (17*i + k) % 32 are all
// distinct across lanes i for any fixed k: conflict-free scalar reads.
// 2-way split accumulator chains to halve the serial FMA depth.
// ---------------------------------------------------------------------------
__global__ __launch_bounds__(256, 1)
void k3_chunk_scan()
{
    float* Ms = smem;             // 64 chunks x 16x17 padded = 17408
    float* vs = smem + 17408;     // 64*16

    const int b   = blockIdx.x;
    const int tid = threadIdx.x;
    for (int i = tid; i < 64 * 256; i += 256) {
        int c = i >> 8, rem = i & 255, row = rem >> 4, col = rem & 15;
        Ms[c * 272 + row * 17 + col] = g_M[(size_t)b * CPB * 256 + i];
    }
    for (int i = tid; i < 256; i += 256)
        ((float4*)vs)[i] = ((const float4*)(g_v + (size_t)b * CPB * DS))[i];
    __syncthreads();

    if (tid < 16) {
        const int i = tid;
        float h = 0.f;
        for (int c = 0; c < CPB; c++) {
            g_h0[((size_t)b * CPB + c) * DS + i] = h;
            const float* Mr = Ms + c * 272 + i * 17;
            float s0 = vs[c * DS + i], s1 = 0.f;
#pragma unroll
            for (int k = 0; k < 16; k += 2) {
                float h0v = __shfl_sync(0x0000FFFFu, h, k,     16);
                float h1v = __shfl_sync(0x0000FFFFu, h, k + 1, 16);
                s0 += Mr[k]     * h0v;
                s1 += Mr[k + 1] * h1v;
            }
            h = s0 + s1;
        }
    }
}

// ---------------------------------------------------------------------------
// K4 (tf32, cp.async pipelined): h_t = M_t h0 + v_t (parallel), then
// CP = x@W_C + b_C, out[t,d] = sum_n h[t,n]*CP[t,n,d].  Block = one chunk.
// ---------------------------------------------------------------------------
__global__ __launch_bounds__(256, 2)
void k4_out(const float* __restrict__ x, const float* __restrict__ bC,
            float* __restrict__ out)
{
    float* xs_t = smem;               // 4352: tf32-rounded x (row-major)
    float* Wf0  = smem + 4352;        // 8704
    float* Wf1  = smem + 13056;       // 8704
    float* hsh  = smem + 21760;       // 1088
    float* bsh  = smem + 22848;       // 1024
    float* h0sh = smem + 23872;       // 16
    float* red  = Wf0;                // reduction buffer (reuse after loop)

    const int tid  = threadIdx.x;
    const int row0 = blockIdx.x * 64;

    // stage chunk 0 of W_C
    {
#pragma unroll
        for (int s = 0; s < 8; s++) {
            int i = tid + s * 256, r = i >> 5, q = i & 31;
            cp16(Wf0 + r * WPAD + q * 4, g_WCt + (size_t)r * 1024 + q * 4);
        }
        cp_commit();
    }

    for (int i = tid; i < 64 * 16; i += 256) {
        int r = i >> 4, c4 = i & 15;
        float4 v = ((const float4*)(x + (size_t)(row0 + r) * DM))[c4];
        ((float4*)(xs_t + r * XPAD))[c4] =
            make_float4(tf32r(v.x), tf32r(v.y), tf32r(v.z), tf32r(v.w));
    }
    for (int i = tid; i < 1024; i += 256) bsh[i] = bC[i];
    if (tid < 16) h0sh[tid] = g_h0[(size_t)blockIdx.x * DS + tid];
    __syncthreads();

    // parallel hs reconstruction from in-place prefixes (overlaps cp.async)
#pragma unroll
    for (int q = 0; q < 4; q++) {
        int idx = tid + q * 256;
        int t = idx >> 4, i = idx & 15;
        const float4* P = (const float4*)&g_A[(size_t)(row0 + t) * 256 + i * 16];
        float4 p0 = P[0], p1 = P[1], p2 = P[2], p3 = P[3];
        float acc = g_Bx[(size_t)(row0 + t) * DS + i];
        acc += p0.x * h0sh[0]  + p0.y * h0sh[1]  + p0.z * h0sh[2]  + p0.w * h0sh[3];
        acc += p1.x * h0sh[4]  + p1.y * h0sh[5]  + p1.z * h0sh[6]  + p1.w * h0sh[7];
        acc += p2.x * h0sh[8]  + p2.y * h0sh[9]  + p2.z * h0sh[10] + p2.w * h0sh[11];
        acc += p3.x * h0sh[12] + p3.y * h0sh[13] + p3.z * h0sh[14] + p3.w * h0sh[15];
        hsh[t * HPAD + i] = acc;
    }
    // hsh visibility: first in-loop __syncthreads below

    const int lane = tid & 31;
    const int g    = lane >> 2;
    const int tg   = lane & 3;
    const int wid  = tid >> 5;
    const int wm   = wid >> 1;
    const int wn   = wid & 1;
    const int rA0  = wm * 16 + g;
    const int rA1  = rA0 + 8;

    float oacc[8][4];
#pragma unroll
    for (int nt = 0; nt < 8; nt++)
#pragma unroll
        for (int j = 0; j < 4; j++) oacc[nt][j] = 0.f;

    for (int c = 0; c < 8; c++) {
        cp_wait_all();
        __syncthreads();

        if (c < 7) {
            float* dst = ((c + 1) & 1) ? Wf1 : Wf0;
#pragma unroll
            for (int s = 0; s < 8; s++) {
                int i = tid + s * 256, r = i >> 5, q = i & 31;
                cp16(dst + r * WPAD + q * 4,
                     g_WCt + (size_t)r * 1024 + (c + 1) * 128 + q * 4);
            }
            cp_commit();
        }

        const float* Wt = (c & 1) ? Wf1 : Wf0;

        float cfr[8][4];
#pragma unroll
        for (int nt = 0; nt < 8; nt++)
#pragma unroll
            for (int j = 0; j < 4; j++) cfr[nt][j] = 0.f;

#pragma unroll
        for (int k = 0; k < 8; k++) {
            float a0 = xs_t[rA0 * XPAD + k * 8 + tg];
            float a1 = xs_t[rA1 * XPAD + k * 8 + tg];
            float a2 = xs_t[rA0 * XPAD + k * 8 + tg + 4];
            float a3 = xs_t[rA1 * XPAD + k * 8 + tg + 4];
#pragma unroll
            for (int nt = 0; nt < 8; nt++) {
                float b0 = Wt[(k * 8 + tg)     * WPAD + wn * 64 + nt * 8 + g];
                float b1 = Wt[(k * 8 + tg + 4) * WPAD + wn * 64 + nt * 8 + g];
                mma_tf32(cfr[nt], a0, a1, a2, a3, b0, b1);
            }
        }

        const int n  = c * 2 + wn;
        const float hg  = hsh[rA0 * HPAD + n];
        const float hg8 = hsh[rA1 * HPAD + n];
#pragma unroll
        for (int nt = 0; nt < 8; nt++) {
            int bcol = c * 128 + wn * 64 + nt * 8 + 2 * tg;
            float b0v = bsh[bcol], b1v = bsh[bcol + 1];
            oacc[nt][0] += hg  * (cfr[nt][0] + b0v);
            oacc[nt][1] += hg  * (cfr[nt][1] + b1v);
            oacc[nt][2] += hg8 * (cfr[nt][2] + b0v);
            oacc[nt][3] += hg8 * (cfr[nt][3] + b1v);
        }
    }

    // combine the wn=0 / wn=1 partial n-sums (same rows, same cols)
    __syncthreads();
    if (wn == 1) {
#pragma unroll
        for (int nt = 0; nt < 8; nt++)
            ((float4*)&red[wm * 1024 + nt * 128 + lane * 4])[0] =
                make_float4(oacc[nt][0], oacc[nt][1], oacc[nt][2], oacc[nt][3]);
    }
    __syncthreads();
    if (wn == 0) {
#pragma unroll
        for (int nt = 0; nt < 8; nt++) {
            float4 p = ((float4*)&red[wm * 1024 + nt * 128 + lane * 4])[0];
            int d = nt * 8 + 2 * tg;
            float2 s0 = make_float2(oacc[nt][0] + p.x, oacc[nt][1] + p.y);
            float2 s1 = make_float2(oacc[nt][2] + p.z, oacc[nt][3] + p.w);
            *(float2*)&out[(size_t)(row0 + rA0) * DM + d] = s0;
            *(float2*)&out[(size_t)(row0 + rA1) * DM + d] = s1;
        }
    }
}

// ---------------------------------------------------------------------------
// Launch
// ---------------------------------------------------------------------------
extern "C" void kernel_launch(void* const* d_in, const int* in_sizes, int n_in,
                              void* d_out, int out_size)
{
    (void)in_sizes; (void)n_in; (void)out_size;
    const float* x  = (const float*)d_in[0];
    const float* WA = (const float*)d_in[1];
    const float* bA = (const float*)d_in[2];
    const float* WB = (const float*)d_in[3];
    const float* bB = (const float*)d_in[4];
    const float* WC = (const float*)d_in[5];
    const float* bC = (const float*)d_in[6];
    float* out = (float*)d_out;

    const int s1 = 24064 * 4;                         // 96,256 B
    const int s2 = (16384 + 1024 + 2*272 + 2*16) * 4; // 71,936 B
    const int s3 = (17408 + 1024) * 4;                // 73,728 B
    const int s4 = 23888 * 4;                         // 95,552 B

    cudaFuncSetAttribute(k1_proj,         cudaFuncAttributeMaxDynamicSharedMemorySize, s1);
    cudaFuncSetAttribute(k2_chunk_prefix, cudaFuncAttributeMaxDynamicSharedMemorySize, s2);
    cudaFuncSetAttribute(k3_chunk_scan,   cudaFuncAttributeMaxDynamicSharedMemorySize, s3);
    cudaFuncSetAttribute(k4_out,          cudaFuncAttributeMaxDynamicSharedMemorySize, s4);

    k0_round       <<<144,    256>>>(WA, WB, WC);
    k1_proj        <<<NCHUNK, 256, s1>>>(x, bA, bB);
    k2_chunk_prefix<<<NCHUNK, 256, s2>>>();
    k3_chunk_scan  <<<BATCH,  256, s3>>>();
    k4_out         <<<NCHUNK, 256, s4>>>(x, bC, out);
}

// round 10
// speedup vs baseline: 1.5539x; 1.5539x over previous
#include <cuda_runtime.h>
#include <cstdint>

// Problem constants
#define BATCH 8
#define SEQ   4096
#define DM    64
#define DS    16
#define ROWS  (BATCH*SEQ)     // 32768 timesteps total
#define CH    64              // chunk length for parallel scan
#define NCHUNK (ROWS/CH)      // 512
#define CPB   (SEQ/CH)        // 64 chunks per batch

#define XPAD 68               // x tile row stride (floats)
#define WPAD 136              // weight tile row stride (floats) — conflict-free
#define HPAD 17               // hs tile row stride

// ---------------------------------------------------------------------------
// Device scratch
// ---------------------------------------------------------------------------
__device__ float g_A  [ROWS*256];   // A_t, then in-place chunk prefixes M_t
__device__ float g_Bx [ROWS*DS];    // Bx_t, then in-place prefixes v_t
__device__ float g_M  [NCHUNK*256];
__device__ float g_v  [NCHUNK*DS];
__device__ float g_h0 [NCHUNK*DS];
__device__ float g_WAt[64*256];     // tf32-rounded weights
__device__ float g_WBt[64*1024];
__device__ float g_WCt[64*1024];

extern __shared__ float smem[];

// ---------------------------------------------------------------------------
// helpers
// ---------------------------------------------------------------------------
__device__ __forceinline__ float tf32r(float v) {
    uint32_t o;
    asm("cvt.rna.tf32.f32 %0, %1;" : "=r"(o) : "f"(v));
    return __uint_as_float(o);
}

__device__ __forceinline__ void mma_tf32(float c[4],
                                         float a0, float a1, float a2, float a3,
                                         float b0, float b1)
{
    asm volatile(
        "mma.sync.aligned.m16n8k8.row.col.f32.tf32.tf32.f32 "
        "{%0,%1,%2,%3}, {%4,%5,%6,%7}, {%8,%9}, {%0,%1,%2,%3};\n"
        : "+f"(c[0]), "+f"(c[1]), "+f"(c[2]), "+f"(c[3])
        : "r"(__float_as_uint(a0)), "r"(__float_as_uint(a1)),
          "r"(__float_as_uint(a2)), "r"(__float_as_uint(a3)),
          "r"(__float_as_uint(b0)), "r"(__float_as_uint(b1)));
}

__device__ __forceinline__ void cp16(float* dst_smem, const float* src) {
    uint32_t d = (uint32_t)__cvta_generic_to_shared(dst_smem);
    asm volatile("cp.async.cg.shared.global [%0], [%1], 16;\n"
                 :: "r"(d), "l"(src));
}
__device__ __forceinline__ void cp_commit() {
    asm volatile("cp.async.commit_group;\n");
}
__device__ __forceinline__ void cp_wait_all() {
    asm volatile("cp.async.wait_group 0;\n");
}

// ---------------------------------------------------------------------------
// K0: one-time tf32 rounding of all weights.
// ---------------------------------------------------------------------------
__global__ __launch_bounds__(256, 4)
void k0_round(const float* __restrict__ WA, const float* __restrict__ WB,
              const float* __restrict__ WC)
{
    int i = blockIdx.x * 256 + threadIdx.x;       // float4 index, 36864 total
    const float* src; float* dst; int off;
    if (i < 4096)       { src = WA; dst = g_WAt; off = i; }
    else if (i < 20480) { src = WB; dst = g_WBt; off = i - 4096; }
    else                { src = WC; dst = g_WCt; off = i - 20480; }
    float4 v = ((const float4*)src)[off];
    ((float4*)dst)[off] = make_float4(tf32r(v.x), tf32r(v.y),
                                      tf32r(v.z), tf32r(v.w));
}

// ---------------------------------------------------------------------------
// K1 (tf32, cp.async pipelined): A = x@W_A + b_A -> g_A ; Bx -> g_Bx.
// Weight chunks (128 cols) stream through a 2-deep cp.async ring.
// ---------------------------------------------------------------------------
__global__ __launch_bounds__(256, 2)
void k1_proj(const float* __restrict__ x,
             const float* __restrict__ bA, const float* __restrict__ bB)
{
    float* xs_f = smem;               // 4352: raw f32 x tile
    float* Wf0  = smem + 4352;        // 8704: weight ring buffer 0
    float* Wf1  = smem + 13056;       // 8704: ring buffer 1
    float* bsh  = smem + 21760;       // 1280: biases (bA then bB)
    float* Bxs  = smem + 23040;       // 1024: Bx tile [64][16]

    const int tid  = threadIdx.x;
    const int row0 = blockIdx.x * 64;

    // stage chunk 0 (W_A cols 0..127) immediately
    {
        float* dst = Wf0;
#pragma unroll
        for (int s = 0; s < 8; s++) {
            int i = tid + s * 256, r = i >> 5, q = i & 31;
            cp16(dst + r * WPAD + q * 4, g_WAt + (size_t)r * 256 + q * 4);
        }
        cp_commit();
    }

    for (int i = tid; i < 64 * 16; i += 256) {
        int r = i >> 4, c4 = i & 15;
        ((float4*)(xs_f + r * XPAD))[c4] =
            ((const float4*)(x + (size_t)(row0 + r) * DM))[c4];
    }
    for (int i = tid; i < 256;  i += 256) bsh[i]       = bA[i];
    for (int i = tid; i < 1024; i += 256) bsh[256 + i] = bB[i];
    __syncthreads();

    const int lane = tid & 31;
    const int g    = lane >> 2;
    const int tg   = lane & 3;
    const int wid  = tid >> 5;
    const int wm   = wid >> 1;
    const int wn   = wid & 1;
    const int rA0  = wm * 16 + g;
    const int rA1  = rA0 + 8;

    // A fragments cached in registers (rounded from raw copy)
    float af[8][4];
#pragma unroll
    for (int k = 0; k < 8; k++) {
        af[k][0] = tf32r(xs_f[rA0 * XPAD + k * 8 + tg]);
        af[k][1] = tf32r(xs_f[rA1 * XPAD + k * 8 + tg]);
        af[k][2] = tf32r(xs_f[rA0 * XPAD + k * 8 + tg + 4]);
        af[k][3] = tf32r(xs_f[rA1 * XPAD + k * 8 + tg + 4]);
    }

    for (int c = 0; c < 10; c++) {
        cp_wait_all();          // chunk c landed
        __syncthreads();        // + all warps done with the other buffer

        // prefetch chunk c+1 into the other buffer (overlaps with MMAs below)
        if (c < 9) {
            float* dst = ((c + 1) & 1) ? Wf1 : Wf0;
            const float* src; int ldw, colbase;
            if (c + 1 < 2) { src = g_WAt; ldw = 256;  colbase = (c + 1) * 128; }
            else           { src = g_WBt; ldw = 1024; colbase = (c - 1) * 128; }
#pragma unroll
            for (int s = 0; s < 8; s++) {
                int i = tid + s * 256, r = i >> 5, q = i & 31;
                cp16(dst + r * WPAD + q * 4,
                     src + (size_t)r * ldw + colbase + q * 4);
            }
            cp_commit();
        }

        const float* Wt = (c & 1) ? Wf1 : Wf0;

        float cfr[8][4];
#pragma unroll
        for (int nt = 0; nt < 8; nt++)
#pragma unroll
            for (int j = 0; j < 4; j++) cfr[nt][j] = 0.f;

#pragma unroll
        for (int k = 0; k < 8; k++) {
#pragma unroll
            for (int nt = 0; nt < 8; nt++) {
                float b0 = Wt[(k * 8 + tg)     * WPAD + wn * 64 + nt * 8 + g];
                float b1 = Wt[(k * 8 + tg + 4) * WPAD + wn * 64 + nt * 8 + g];
                mma_tf32(cfr[nt], af[k][0], af[k][1], af[k][2], af[k][3], b0, b1);
            }
        }

        if (c < 2) {
            // A-projection: add bias, store raw A_t (unique writer/element)
#pragma unroll
            for (int nt = 0; nt < 8; nt++) {
                int gcol = c * 128 + wn * 64 + nt * 8 + 2 * tg;
                float b0v = bsh[gcol], b1v = bsh[gcol + 1];
                float2 s0 = make_float2(cfr[nt][0] + b0v, cfr[nt][1] + b1v);
                float2 s1 = make_float2(cfr[nt][2] + b0v, cfr[nt][3] + b1v);
                *(float2*)&g_A[(size_t)(row0 + rA0) * 256 + gcol] = s0;
                *(float2*)&g_A[(size_t)(row0 + rA1) * 256 + gcol] = s1;
            }
        } else {
            // B-projection: contract with raw x over d, reduce over quad
            const int n = (c - 2) * 2 + wn;
            float pg = 0.f, pg8 = 0.f;
#pragma unroll
            for (int nt = 0; nt < 8; nt++) {
                int bcol = (c - 2) * 128 + wn * 64 + nt * 8 + 2 * tg;
                int d    = nt * 8 + 2 * tg;
                float b0v = bsh[256 + bcol], b1v = bsh[256 + bcol + 1];
                pg  += (cfr[nt][0] + b0v) * xs_f[rA0 * XPAD + d]
                     + (cfr[nt][1] + b1v) * xs_f[rA0 * XPAD + d + 1];
                pg8 += (cfr[nt][2] + b0v) * xs_f[rA1 * XPAD + d]
                     + (cfr[nt][3] + b1v) * xs_f[rA1 * XPAD + d + 1];
            }
            pg  += __shfl_xor_sync(0xffffffffu, pg,  1);
            pg  += __shfl_xor_sync(0xffffffffu, pg,  2);
            pg8 += __shfl_xor_sync(0xffffffffu, pg8, 1);
            pg8 += __shfl_xor_sync(0xffffffffu, pg8, 2);
            if (tg == 0) {
                Bxs[rA0 * 16 + n] = pg;
                Bxs[rA1 * 16 + n] = pg8;
            }
        }
    }
    __syncthreads();
    for (int i = tid; i < 64 * DS; i += 256)
        g_Bx[(size_t)row0 * DS + i] = Bxs[i];
}

// ---------------------------------------------------------------------------
// K2: per-chunk prefix scan; overwrites g_A / g_Bx in place, summary to g_M/g_v.
// ---------------------------------------------------------------------------
__global__ __launch_bounds__(256, 1)
void k2_chunk_prefix()
{
    float* As  = smem;            // 16384 floats
    float* Bxs = smem + 16384;    // 1024
    float* Msh = smem + 17408;    // 2 x 272
    float* vsh = smem + 17952;    // 2 x 16

    const int tid   = threadIdx.x;
    const int chunk = blockIdx.x;
    const size_t base = (size_t)chunk * CH;

    for (int i = tid; i < 4096; i += 256)
        ((float4*)As)[i] = ((const float4*)(g_A + base * 256))[i];
    for (int i = tid; i < 256; i += 256)
        ((float4*)Bxs)[i] = ((const float4*)(g_Bx + base * DS))[i];
    __syncthreads();

    const int i = tid >> 4, j = tid & 15;
    Msh[i * 17 + j] = As[i * 16 + j];
    if (j == 0) vsh[i] = Bxs[i];
    __syncthreads();

    for (int t = 1; t < CH; t++) {
        const int cur = t & 1, prev = cur ^ 1;
        const float* Ar = As + t * 256 + i * 16;
        const float* Mp = Msh + prev * 272;
        float s0 = 0.f, s1 = 0.f;
#pragma unroll
        for (int k = 0; k < 16; k += 2) {
            s0 += Ar[k]     * Mp[k * 17 + j];
            s1 += Ar[k + 1] * Mp[(k + 1) * 17 + j];
        }
        float nm = s0 + s1;
        Msh[cur * 272 + i * 17 + j] = nm;
        g_A[(base + t) * 256 + tid] = nm;
        if (j == 0) {
            const float* vp = vsh + prev * 16;
            float nv = Bxs[t * DS + i];
#pragma unroll
            for (int k = 0; k < 16; k++) nv += Ar[k] * vp[k];
            vsh[cur * 16 + i] = nv;
            g_Bx[(base + t) * DS + i] = nv;
        }
        __syncthreads();
    }

    const int f = (CH - 1) & 1;
    g_M[(size_t)chunk * 256 + tid] = Msh[f * 272 + i * 17 + j];
    if (j == 0) g_v[(size_t)chunk * DS + i] = vsh[f * 16 + i];
}

// ---------------------------------------------------------------------------
// K3: sequential prefix over chunk summaries (64 per batch). One block/batch.
// M tile staged with 17-float row pitch: banks (17*i + k) % 32 all distinct
// across lanes i for fixed k -> conflict-free scalar reads in the scan loop.
// ---------------------------------------------------------------------------
__global__ __launch_bounds__(256, 1)
void k3_chunk_scan()
{
    float* Ms = smem;             // 64 chunks x 16x17 padded = 17408
    float* vs = smem + 17408;     // 64*16

    const int b   = blockIdx.x;
    const int tid = threadIdx.x;
    for (int i = tid; i < 64 * 256; i += 256) {
        int c = i >> 8, rem = i & 255, row = rem >> 4, col = rem & 15;
        Ms[c * 272 + row * 17 + col] = g_M[(size_t)b * CPB * 256 + i];
    }
    for (int i = tid; i < 256; i += 256)
        ((float4*)vs)[i] = ((const float4*)(g_v + (size_t)b * CPB * DS))[i];
    __syncthreads();

    if (tid < 16) {
        const int i = tid;
        float h = 0.f;
        for (int c = 0; c < CPB; c++) {
            g_h0[((size_t)b * CPB + c) * DS + i] = h;
            const float* Mr = Ms + c * 272 + i * 17;
            float s0 = vs[c * DS + i], s1 = 0.f;
#pragma unroll
            for (int k = 0; k < 16; k += 2) {
                float h0v = __shfl_sync(0x0000FFFFu, h, k,     16);
                float h1v = __shfl_sync(0x0000FFFFu, h, k + 1, 16);
                s0 += Mr[k]     * h0v;
                s1 += Mr[k + 1] * h1v;
            }
            h = s0 + s1;
        }
    }
}

// ---------------------------------------------------------------------------
// K4 (tf32, cp.async pipelined): h_t = M_t h0 + v_t (parallel), then
// CP = x@W_C + b_C, out[t,d] = sum_n h[t,n]*CP[t,n,d].  Block = one chunk.
// ---------------------------------------------------------------------------
__global__ __launch_bounds__(256, 2)
void k4_out(const float* __restrict__ x, const float* __restrict__ bC,
            float* __restrict__ out)
{
    float* xs_t = smem;               // 4352: tf32-rounded x (row-major)
    float* Wf0  = smem + 4352;        // 8704
    float* Wf1  = smem + 13056;       // 8704
    float* hsh  = smem + 21760;       // 1088
    float* bsh  = smem + 22848;       // 1024
    float* h0sh = smem + 23872;       // 16
    float* red  = Wf0;                // reduction buffer (reuse after loop)

    const int tid  = threadIdx.x;
    const int row0 = blockIdx.x * 64;

    // stage chunk 0 of W_C
    {
#pragma unroll
        for (int s = 0; s < 8; s++) {
            int i = tid + s * 256, r = i >> 5, q = i & 31;
            cp16(Wf0 + r * WPAD + q * 4, g_WCt + (size_t)r * 1024 + q * 4);
        }
        cp_commit();
    }

    for (int i = tid; i < 64 * 16; i += 256) {
        int r = i >> 4, c4 = i & 15;
        float4 v = ((const float4*)(x + (size_t)(row0 + r) * DM))[c4];
        ((float4*)(xs_t + r * XPAD))[c4] =
            make_float4(tf32r(v.x), tf32r(v.y), tf32r(v.z), tf32r(v.w));
    }
    for (int i = tid; i < 1024; i += 256) bsh[i] = bC[i];
    if (tid < 16) h0sh[tid] = g_h0[(size_t)blockIdx.x * DS + tid];
    __syncthreads();

    // parallel hs reconstruction from in-place prefixes (overlaps cp.async)
#pragma unroll
    for (int q = 0; q < 4; q++) {
        int idx = tid + q * 256;
        int t = idx >> 4, i = idx & 15;
        const float4* P = (const float4*)&g_A[(size_t)(row0 + t) * 256 + i * 16];
        float4 p0 = P[0], p1 = P[1], p2 = P[2], p3 = P[3];
        float acc = g_Bx[(size_t)(row0 + t) * DS + i];
        acc += p0.x * h0sh[0]  + p0.y * h0sh[1]  + p0.z * h0sh[2]  + p0.w * h0sh[3];
        acc += p1.x * h0sh[4]  + p1.y * h0sh[5]  + p1.z * h0sh[6]  + p1.w * h0sh[7];
        acc += p2.x * h0sh[8]  + p2.y * h0sh[9]  + p2.z * h0sh[10] + p2.w * h0sh[11];
        acc += p3.x * h0sh[12] + p3.y * h0sh[13] + p3.z * h0sh[14] + p3.w * h0sh[15];
        hsh[t * HPAD + i] = acc;
    }
    // hsh visibility: first in-loop __syncthreads below

    const int lane = tid & 31;
    const int g    = lane >> 2;
    const int tg   = lane & 3;
    const int wid  = tid >> 5;
    const int wm   = wid >> 1;
    const int wn   = wid & 1;
    const int rA0  = wm * 16 + g;
    const int rA1  = rA0 + 8;

    float oacc[8][4];
#pragma unroll
    for (int nt = 0; nt < 8; nt++)
#pragma unroll
        for (int j = 0; j < 4; j++) oacc[nt][j] = 0.f;

    for (int c = 0; c < 8; c++) {
        cp_wait_all();
        __syncthreads();

        if (c < 7) {
            float* dst = ((c + 1) & 1) ? Wf1 : Wf0;
#pragma unroll
            for (int s = 0; s < 8; s++) {
                int i = tid + s * 256, r = i >> 5, q = i & 31;
                cp16(dst + r * WPAD + q * 4,
                     g_WCt + (size_t)r * 1024 + (c + 1) * 128 + q * 4);
            }
            cp_commit();
        }

        const float* Wt = (c & 1) ? Wf1 : Wf0;

        float cfr[8][4];
#pragma unroll
        for (int nt = 0; nt < 8; nt++)
#pragma unroll
            for (int j = 0; j < 4; j++) cfr[nt][j] = 0.f;

#pragma unroll
        for (int k = 0; k < 8; k++) {
            float a0 = xs_t[rA0 * XPAD + k * 8 + tg];
            float a1 = xs_t[rA1 * XPAD + k * 8 + tg];
            float a2 = xs_t[rA0 * XPAD + k * 8 + tg + 4];
            float a3 = xs_t[rA1 * XPAD + k * 8 + tg + 4];
#pragma unroll
            for (int nt = 0; nt < 8; nt++) {
                float b0 = Wt[(k * 8 + tg)     * WPAD + wn * 64 + nt * 8 + g];
                float b1 = Wt[(k * 8 + tg + 4) * WPAD + wn * 64 + nt * 8 + g];
                mma_tf32(cfr[nt], a0, a1, a2, a3, b0, b1);
            }
        }

        const int n  = c * 2 + wn;
        const float hg  = hsh[rA0 * HPAD + n];
        const float hg8 = hsh[rA1 * HPAD + n];
#pragma unroll
        for (int nt = 0; nt < 8; nt++) {
            int bcol = c * 128 + wn * 64 + nt * 8 + 2 * tg;
            float b0v = bsh[bcol], b1v = bsh[bcol + 1];
            oacc[nt][0] += hg  * (cfr[nt][0] + b0v);
            oacc[nt][1] += hg  * (cfr[nt][1] + b1v);
            oacc[nt][2] += hg8 * (cfr[nt][2] + b0v);
            oacc[nt][3] += hg8 * (cfr[nt][3] + b1v);
        }
    }

    // combine the wn=0 / wn=1 partial n-sums (same rows, same cols)
    __syncthreads();
    if (wn == 1) {
#pragma unroll
        for (int nt = 0; nt < 8; nt++)
            ((float4*)&red[wm * 1024 + nt * 128 + lane * 4])[0] =
                make_float4(oacc[nt][0], oacc[nt][1], oacc[nt][2], oacc[nt][3]);
    }
    __syncthreads();
    if (wn == 0) {
#pragma unroll
        for (int nt = 0; nt < 8; nt++) {
            float4 p = ((float4*)&red[wm * 1024 + nt * 128 + lane * 4])[0];
            int d = nt * 8 + 2 * tg;
            float2 s0 = make_float2(oacc[nt][0] + p.x, oacc[nt][1] + p.y);
            float2 s1 = make_float2(oacc[nt][2] + p.z, oacc[nt][3] + p.w);
            *(float2*)&out[(size_t)(row0 + rA0) * DM + d] = s0;
            *(float2*)&out[(size_t)(row0 + rA1) * DM + d] = s1;
        }
    }
}

// ---------------------------------------------------------------------------
// Launch
// ---------------------------------------------------------------------------
extern "C" void kernel_launch(void* const* d_in, const int* in_sizes, int n_in,
                              void* d_out, int out_size)
{
    (void)in_sizes; (void)n_in; (void)out_size;
    const float* x  = (const float*)d_in[0];
    const float* WA = (const float*)d_in[1];
    const float* bA = (const float*)d_in[2];
    const float* WB = (const float*)d_in[3];
    const float* bB = (const float*)d_in[4];
    const float* WC = (const float*)d_in[5];
    const float* bC = (const float*)d_in[6];
    float* out = (float*)d_out;

    const int s1 = 24064 * 4;                         // 96,256 B
    const int s2 = (16384 + 1024 + 2*272 + 2*16) * 4; // 71,936 B
    const int s3 = (17408 + 1024) * 4;                // 73,728 B
    const int s4 = 23888 * 4;                         // 95,552 B

    cudaFuncSetAttribute(k1_proj,         cudaFuncAttributeMaxDynamicSharedMemorySize, s1);
    cudaFuncSetAttribute(k2_chunk_prefix, cudaFuncAttributeMaxDynamicSharedMemorySize, s2);
    cudaFuncSetAttribute(k3_chunk_scan,   cudaFuncAttributeMaxDynamicSharedMemorySize, s3);
    cudaFuncSetAttribute(k4_out,          cudaFuncAttributeMaxDynamicSharedMemorySize, s4);

    k0_round       <<<144,    256>>>(WA, WB, WC);
    k1_proj        <<<NCHUNK, 256, s1>>>(x, bA, bB);
    k2_chunk_prefix<<<NCHUNK, 256, s2>>>();
    k3_chunk_scan  <<<BATCH,  256, s3>>>();
    k4_out         <<<NCHUNK, 256, s4>>>(x, bC, out);
}

// round 12
// speedup vs baseline: 1.6176x; 1.0410x over previous
#include <cuda_runtime.h>
#include <cstdint>

// Problem constants
#define BATCH 8
#define SEQ   4096
#define DM    64
#define DS    16
#define ROWS  (BATCH*SEQ)     // 32768 timesteps total
#define CH    64              // chunk length for parallel scan
#define NCHUNK (ROWS/CH)      // 512
#define CPB   (SEQ/CH)        // 64 chunks per batch

#define XPAD 68               // x tile row stride (floats)
#define WPAD 136              // weight tile row stride (floats) — conflict-free
#define HPAD 17               // hs tile row stride

// ---------------------------------------------------------------------------
// Device scratch
// ---------------------------------------------------------------------------
__device__ float g_A  [ROWS*256];   // A_t, then in-place chunk prefixes M_t
__device__ float g_Bx [ROWS*DS];    // Bx_t, then in-place prefixes v_t
__device__ float g_M  [NCHUNK*256];
__device__ float g_v  [NCHUNK*DS];
__device__ float g_h0 [NCHUNK*DS];
__device__ float g_WAt[64*256];     // tf32-rounded weights
__device__ float g_WBt[64*1024];
__device__ float g_WCt[64*1024];

extern __shared__ float smem[];

// ---------------------------------------------------------------------------
// helpers
// ---------------------------------------------------------------------------
__device__ __forceinline__ float tf32r(float v) {
    uint32_t o;
    asm("cvt.rna.tf32.f32 %0, %1;" : "=r"(o) : "f"(v));
    return __uint_as_float(o);
}

__device__ __forceinline__ void mma_tf32(float c[4],
                                         float a0, float a1, float a2, float a3,
                                         float b0, float b1)
{
    asm volatile(
        "mma.sync.aligned.m16n8k8.row.col.f32.tf32.tf32.f32 "
        "{%0,%1,%2,%3}, {%4,%5,%6,%7}, {%8,%9}, {%0,%1,%2,%3};\n"
        : "+f"(c[0]), "+f"(c[1]), "+f"(c[2]), "+f"(c[3])
        : "r"(__float_as_uint(a0)), "r"(__float_as_uint(a1)),
          "r"(__float_as_uint(a2)), "r"(__float_as_uint(a3)),
          "r"(__float_as_uint(b0)), "r"(__float_as_uint(b1)));
}

__device__ __forceinline__ void cp16(float* dst_smem, const float* src) {
    uint32_t d = (uint32_t)__cvta_generic_to_shared(dst_smem);
    asm volatile("cp.async.cg.shared.global [%0], [%1], 16;\n"
                 :: "r"(d), "l"(src));
}
__device__ __forceinline__ void cp_commit() {
    asm volatile("cp.async.commit_group;\n");
}
__device__ __forceinline__ void cp_wait_all() {
    asm volatile("cp.async.wait_group 0;\n");
}
template<int N> __device__ __forceinline__ void cp_wait_group() {
    asm volatile("cp.async.wait_group %0;\n" :: "n"(N));
}

// ---------------------------------------------------------------------------
// K0: one-time tf32 rounding of all weights.
// ---------------------------------------------------------------------------
__global__ __launch_bounds__(256, 4)
void k0_round(const float* __restrict__ WA, const float* __restrict__ WB,
              const float* __restrict__ WC)
{
    int i = blockIdx.x * 256 + threadIdx.x;       // float4 index, 36864 total
    const float* src; float* dst; int off;
    if (i < 4096)       { src = WA; dst = g_WAt; off = i; }
    else if (i < 20480) { src = WB; dst = g_WBt; off = i - 4096; }
    else                { src = WC; dst = g_WCt; off = i - 20480; }
    float4 v = ((const float4*)src)[off];
    ((float4*)dst)[off] = make_float4(tf32r(v.x), tf32r(v.y),
                                      tf32r(v.z), tf32r(v.w));
}

// ---------------------------------------------------------------------------
// K1 (tf32, cp.async pipelined): A = x@W_A + b_A -> g_A ; Bx -> g_Bx.
// (byte-identical to the proven 170.5 us version)
// ---------------------------------------------------------------------------
__global__ __launch_bounds__(256, 2)
void k1_proj(const float* __restrict__ x,
             const float* __restrict__ bA, const float* __restrict__ bB)
{
    float* xs_f = smem;               // 4352: raw f32 x tile
    float* Wf0  = smem + 4352;        // 8704: weight ring buffer 0
    float* Wf1  = smem + 13056;       // 8704: ring buffer 1
    float* bsh  = smem + 21760;       // 1280: biases (bA then bB)
    float* Bxs  = smem + 23040;       // 1024: Bx tile [64][16]

    const int tid  = threadIdx.x;
    const int row0 = blockIdx.x * 64;

    // stage chunk 0 (W_A cols 0..127) immediately
    {
        float* dst = Wf0;
#pragma unroll
        for (int s = 0; s < 8; s++) {
            int i = tid + s * 256, r = i >> 5, q = i & 31;
            cp16(dst + r * WPAD + q * 4, g_WAt + (size_t)r * 256 + q * 4);
        }
        cp_commit();
    }

    for (int i = tid; i < 64 * 16; i += 256) {
        int r = i >> 4, c4 = i & 15;
        ((float4*)(xs_f + r * XPAD))[c4] =
            ((const float4*)(x + (size_t)(row0 + r) * DM))[c4];
    }
    for (int i = tid; i < 256;  i += 256) bsh[i]       = bA[i];
    for (int i = tid; i < 1024; i += 256) bsh[256 + i] = bB[i];
    __syncthreads();

    const int lane = tid & 31;
    const int g    = lane >> 2;
    const int tg   = lane & 3;
    const int wid  = tid >> 5;
    const int wm   = wid >> 1;
    const int wn   = wid & 1;
    const int rA0  = wm * 16 + g;
    const int rA1  = rA0 + 8;

    // A fragments cached in registers (rounded from raw copy)
    float af[8][4];
#pragma unroll
    for (int k = 0; k < 8; k++) {
        af[k][0] = tf32r(xs_f[rA0 * XPAD + k * 8 + tg]);
        af[k][1] = tf32r(xs_f[rA1 * XPAD + k * 8 + tg]);
        af[k][2] = tf32r(xs_f[rA0 * XPAD + k * 8 + tg + 4]);
        af[k][3] = tf32r(xs_f[rA1 * XPAD + k * 8 + tg + 4]);
    }

    for (int c = 0; c < 10; c++) {
        cp_wait_all();          // chunk c landed
        __syncthreads();        // + all warps done with the other buffer

        // prefetch chunk c+1 into the other buffer (overlaps with MMAs below)
        if (c < 9) {
            float* dst = ((c + 1) & 1) ? Wf1 : Wf0;
            const float* src; int ldw, colbase;
            if (c + 1 < 2) { src = g_WAt; ldw = 256;  colbase = (c + 1) * 128; }
            else           { src = g_WBt; ldw = 1024; colbase = (c - 1) * 128; }
#pragma unroll
            for (int s = 0; s < 8; s++) {
                int i = tid + s * 256, r = i >> 5, q = i & 31;
                cp16(dst + r * WPAD + q * 4,
                     src + (size_t)r * ldw + colbase + q * 4);
            }
            cp_commit();
        }

        const float* Wt = (c & 1) ? Wf1 : Wf0;

        float cfr[8][4];
#pragma unroll
        for (int nt = 0; nt < 8; nt++)
#pragma unroll
            for (int j = 0; j < 4; j++) cfr[nt][j] = 0.f;

#pragma unroll
        for (int k = 0; k < 8; k++) {
#pragma unroll
            for (int nt = 0; nt < 8; nt++) {
                float b0 = Wt[(k * 8 + tg)     * WPAD + wn * 64 + nt * 8 + g];
                float b1 = Wt[(k * 8 + tg + 4) * WPAD + wn * 64 + nt * 8 + g];
                mma_tf32(cfr[nt], af[k][0], af[k][1], af[k][2], af[k][3], b0, b1);
            }
        }

        if (c < 2) {
            // A-projection: add bias, store raw A_t (unique writer/element)
#pragma unroll
            for (int nt = 0; nt < 8; nt++) {
                int gcol = c * 128 + wn * 64 + nt * 8 + 2 * tg;
                float b0v = bsh[gcol], b1v = bsh[gcol + 1];
                float2 s0 = make_float2(cfr[nt][0] + b0v, cfr[nt][1] + b1v);
                float2 s1 = make_float2(cfr[nt][2] + b0v, cfr[nt][3] + b1v);
                *(float2*)&g_A[(size_t)(row0 + rA0) * 256 + gcol] = s0;
                *(float2*)&g_A[(size_t)(row0 + rA1) * 256 + gcol] = s1;
            }
        } else {
            // B-projection: contract with raw x over d, reduce over quad
            const int n = (c - 2) * 2 + wn;
            float pg = 0.f, pg8 = 0.f;
#pragma unroll
            for (int nt = 0; nt < 8; nt++) {
                int bcol = (c - 2) * 128 + wn * 64 + nt * 8 + 2 * tg;
                int d    = nt * 8 + 2 * tg;
                float b0v = bsh[256 + bcol], b1v = bsh[256 + bcol + 1];
                pg  += (cfr[nt][0] + b0v) * xs_f[rA0 * XPAD + d]
                     + (cfr[nt][1] + b1v) * xs_f[rA0 * XPAD + d + 1];
                pg8 += (cfr[nt][2] + b0v) * xs_f[rA1 * XPAD + d]
                     + (cfr[nt][3] + b1v) * xs_f[rA1 * XPAD + d + 1];
            }
            pg  += __shfl_xor_sync(0xffffffffu, pg,  1);
            pg  += __shfl_xor_sync(0xffffffffu, pg,  2);
            pg8 += __shfl_xor_sync(0xffffffffu, pg8, 1);
            pg8 += __shfl_xor_sync(0xffffffffu, pg8, 2);
            if (tg == 0) {
                Bxs[rA0 * 16 + n] = pg;
                Bxs[rA1 * 16 + n] = pg8;
            }
        }
    }
    __syncthreads();
    for (int i = tid; i < 64 * DS; i += 256)
        g_Bx[(size_t)row0 * DS + i] = Bxs[i];
}

// ---------------------------------------------------------------------------
// K2 (v3): per-chunk prefix scan with a 4-deep x 8-step cp.async ring for A.
// FIX vs v2: prologue stages FOUR segments (0..3); steady state stages seg+3
// for seg in [1,4]; tail waits step down. (v2 never staged segment 3.)
// ---------------------------------------------------------------------------
__global__ __launch_bounds__(256, 4)
void k2_chunk_prefix()
{
    float* ring = smem;            // 4 segments x 2048 floats (8 steps each)
    float* Bxs  = smem + 8192;     // 1024
    float* Msh  = smem + 9216;     // 2 x 272
    float* vsh  = smem + 9760;     // 2 x 16

    const int tid   = threadIdx.x;
    const int chunk = blockIdx.x;
    const size_t base = (size_t)chunk * CH;
    const float* Asrc = g_A + base * 256;

    // prologue: stage segments 0..3 (one commit group each)
#pragma unroll
    for (int s = 0; s < 4; s++) {
        float* dst = ring + s * 2048;
        const float* src = Asrc + s * 2048;
        cp16(dst + tid * 4,           src + tid * 4);
        cp16(dst + (tid + 256) * 4,   src + (tid + 256) * 4);
        cp_commit();
    }

    for (int i = tid; i < 256; i += 256)
        ((float4*)Bxs)[i] = ((const float4*)(g_Bx + base * DS))[i];

    cp_wait_group<3>();           // segment 0 landed
    __syncthreads();              // all threads' copies + Bxs visible

    const int i = tid >> 4, j = tid & 15;
    Msh[i * 17 + j] = ring[i * 16 + j];      // M_0 = A_0
    if (j == 0) vsh[i] = Bxs[i];
    __syncthreads();

    for (int t = 1; t < CH; t++) {
        const int seg = t >> 3;
        if ((t & 7) == 0) {
            // entering segment `seg`: stage seg+3 into the slot of seg-1
            // (fully consumed behind the previous step's barrier), then
            // guarantee segment `seg` has landed before reading it.
            if (seg <= 4) {
                float* dst = ring + ((seg + 3) & 3) * 2048;
                const float* src = Asrc + (seg + 3) * 2048;
                cp16(dst + tid * 4,         src + tid * 4);
                cp16(dst + (tid + 256) * 4, src + (tid + 256) * 4);
                cp_commit();
                cp_wait_group<3>();
            } else if (seg == 5) {
                cp_wait_group<2>();
            } else if (seg == 6) {
                cp_wait_group<1>();
            } else {              // seg == 7
                cp_wait_group<0>();
            }
            __syncthreads();      // copies from all threads visible
        }

        const int cur = t & 1, prev = cur ^ 1;
        const float* Ar = ring + (seg & 3) * 2048 + (t & 7) * 256 + i * 16;
        const float* Mp = Msh + prev * 272;
        float s0 = 0.f, s1 = 0.f;
#pragma unroll
        for (int k = 0; k < 16; k += 2) {
            s0 += Ar[k]     * Mp[k * 17 + j];
            s1 += Ar[k + 1] * Mp[(k + 1) * 17 + j];
        }
        float nm = s0 + s1;
        Msh[cur * 272 + i * 17 + j] = nm;
        g_A[(base + t) * 256 + tid] = nm;
        if (j == 0) {
            const float* vp = vsh + prev * 16;
            float nv = Bxs[t * DS + i];
#pragma unroll
            for (int k = 0; k < 16; k++) nv += Ar[k] * vp[k];
            vsh[cur * 16 + i] = nv;
            g_Bx[(base + t) * DS + i] = nv;
        }
        __syncthreads();
    }

    const int f = (CH - 1) & 1;
    g_M[(size_t)chunk * 256 + tid] = Msh[f * 272 + i * 17 + j];
    if (j == 0) g_v[(size_t)chunk * DS + i] = vsh[f * 16 + i];
}

// ---------------------------------------------------------------------------
// K3 (v2): sequential prefix over chunk summaries. One block/batch.
// 17-float row pitch (conflict-free) + register double-buffered prefetch of
// the next chunk's M row, lifting all LDS out of the serial dependence chain.
// ---------------------------------------------------------------------------
__global__ __launch_bounds__(256, 1)
void k3_chunk_scan()
{
    float* Ms = smem;             // 64 chunks x 16x17 padded = 17408
    float* vs = smem + 17408;     // 64*16

    const int b   = blockIdx.x;
    const int tid = threadIdx.x;
    for (int i = tid; i < 64 * 256; i += 256) {
        int c = i >> 8, rem = i & 255, row = rem >> 4, col = rem & 15;
        Ms[c * 272 + row * 17 + col] = g_M[(size_t)b * CPB * 256 + i];
    }
    for (int i = tid; i < 256; i += 256)
        ((float4*)vs)[i] = ((const float4*)(g_v + (size_t)b * CPB * DS))[i];
    __syncthreads();

    if (tid < 16) {
        const int i = tid;
        float mr[16];
#pragma unroll
        for (int k = 0; k < 16; k++) mr[k] = Ms[i * 17 + k];
        float bx = vs[i];
        float h  = 0.f;

        for (int c = 0; c < CPB; c++) {
            g_h0[((size_t)b * CPB + c) * DS + i] = h;

            float nmr[16]; float nbx = 0.f;
            if (c < CPB - 1) {
                const float* Mr = Ms + (c + 1) * 272 + i * 17;
#pragma unroll
                for (int k = 0; k < 16; k++) nmr[k] = Mr[k];
                nbx = vs[(c + 1) * 16 + i];
            } else {
#pragma unroll
                for (int k = 0; k < 16; k++) nmr[k] = 0.f;
            }

            float s0 = bx, s1 = 0.f, s2 = 0.f, s3 = 0.f;
#pragma unroll
            for (int k = 0; k < 16; k += 4) {
                s0 += mr[k]     * __shfl_sync(0x0000FFFFu, h, k,     16);
                s1 += mr[k + 1] * __shfl_sync(0x0000FFFFu, h, k + 1, 16);
                s2 += mr[k + 2] * __shfl_sync(0x0000FFFFu, h, k + 2, 16);
                s3 += mr[k + 3] * __shfl_sync(0x0000FFFFu, h, k + 3, 16);
            }
            h = (s0 + s1) + (s2 + s3);

#pragma unroll
            for (int k = 0; k < 16; k++) mr[k] = nmr[k];
            bx = nbx;
        }
    }
}

// ---------------------------------------------------------------------------
// K4 (tf32, cp.async pipelined): h_t = M_t h0 + v_t (parallel), then
// CP = x@W_C + b_C, out[t,d] = sum_n h[t,n]*CP[t,n,d].  Block = one chunk.
// (byte-identical to the proven 170.5 us version)
// ---------------------------------------------------------------------------
__global__ __launch_bounds__(256, 2)
void k4_out(const float* __restrict__ x, const float* __restrict__ bC,
            float* __restrict__ out)
{
    float* xs_t = smem;               // 4352: tf32-rounded x (row-major)
    float* Wf0  = smem + 4352;        // 8704
    float* Wf1  = smem + 13056;       // 8704
    float* hsh  = smem + 21760;       // 1088
    float* bsh  = smem + 22848;       // 1024
    float* h0sh = smem + 23872;       // 16
    float* red  = Wf0;                // reduction buffer (reuse after loop)

    const int tid  = threadIdx.x;
    const int row0 = blockIdx.x * 64;

    // stage chunk 0 of W_C
    {
#pragma unroll
        for (int s = 0; s < 8; s++) {
            int i = tid + s * 256, r = i >> 5, q = i & 31;
            cp16(Wf0 + r * WPAD + q * 4, g_WCt + (size_t)r * 1024 + q * 4);
        }
        cp_commit();
    }

    for (int i = tid; i < 64 * 16; i += 256) {
        int r = i >> 4, c4 = i & 15;
        float4 v = ((const float4*)(x + (size_t)(row0 + r) * DM))[c4];
        ((float4*)(xs_t + r * XPAD))[c4] =
            make_float4(tf32r(v.x), tf32r(v.y), tf32r(v.z), tf32r(v.w));
    }
    for (int i = tid; i < 1024; i += 256) bsh[i] = bC[i];
    if (tid < 16) h0sh[tid] = g_h0[(size_t)blockIdx.x * DS + tid];
    __syncthreads();

    // parallel hs reconstruction from in-place prefixes (overlaps cp.async)
#pragma unroll
    for (int q = 0; q < 4; q++) {
        int idx = tid + q * 256;
        int t = idx >> 4, i = idx & 15;
        const float4* P = (const float4*)&g_A[(size_t)(row0 + t) * 256 + i * 16];
        float4 p0 = P[0], p1 = P[1], p2 = P[2], p3 = P[3];
        float acc = g_Bx[(size_t)(row0 + t) * DS + i];
        acc += p0.x * h0sh[0]  + p0.y * h0sh[1]  + p0.z * h0sh[2]  + p0.w * h0sh[3];
        acc += p1.x * h0sh[4]  + p1.y * h0sh[5]  + p1.z * h0sh[6]  + p1.w * h0sh[7];
        acc += p2.x * h0sh[8]  + p2.y * h0sh[9]  + p2.z * h0sh[10] + p2.w * h0sh[11];
        acc += p3.x * h0sh[12] + p3.y * h0sh[13] + p3.z * h0sh[14] + p3.w * h0sh[15];
        hsh[t * HPAD + i] = acc;
    }
    // hsh visibility: first in-loop __syncthreads below

    const int lane = tid & 31;
    const int g    = lane >> 2;
    const int tg   = lane & 3;
    const int wid  = tid >> 5;
    const int wm   = wid >> 1;
    const int wn   = wid & 1;
    const int rA0  = wm * 16 + g;
    const int rA1  = rA0 + 8;

    float oacc[8][4];
#pragma unroll
    for (int nt = 0; nt < 8; nt++)
#pragma unroll
        for (int j = 0; j < 4; j++) oacc[nt][j] = 0.f;

    for (int c = 0; c < 8; c++) {
        cp_wait_all();
        __syncthreads();

        if (c < 7) {
            float* dst = ((c + 1) & 1) ? Wf1 : Wf0;
#pragma unroll
            for (int s = 0; s < 8; s++) {
                int i = tid + s * 256, r = i >> 5, q = i & 31;
                cp16(dst + r * WPAD + q * 4,
                     g_WCt + (size_t)r * 1024 + (c + 1) * 128 + q * 4);
            }
            cp_commit();
        }

        const float* Wt = (c & 1) ? Wf1 : Wf0;

        float cfr[8][4];
#pragma unroll
        for (int nt = 0; nt < 8; nt++)
#pragma unroll
            for (int j = 0; j < 4; j++) cfr[nt][j] = 0.f;

#pragma unroll
        for (int k = 0; k < 8; k++) {
            float a0 = xs_t[rA0 * XPAD + k * 8 + tg];
            float a1 = xs_t[rA1 * XPAD + k * 8 + tg];
            float a2 = xs_t[rA0 * XPAD + k * 8 + tg + 4];
            float a3 = xs_t[rA1 * XPAD + k * 8 + tg + 4];
#pragma unroll
            for (int nt = 0; nt < 8; nt++) {
                float b0 = Wt[(k * 8 + tg)     * WPAD + wn * 64 + nt * 8 + g];
                float b1 = Wt[(k * 8 + tg + 4) * WPAD + wn * 64 + nt * 8 + g];
                mma_tf32(cfr[nt], a0, a1, a2, a3, b0, b1);
            }
        }

        const int n  = c * 2 + wn;
        const float hg  = hsh[rA0 * HPAD + n];
        const float hg8 = hsh[rA1 * HPAD + n];
#pragma unroll
        for (int nt = 0; nt < 8; nt++) {
            int bcol = c * 128 + wn * 64 + nt * 8 + 2 * tg;
            float b0v = bsh[bcol], b1v = bsh[bcol + 1];
            oacc[nt][0] += hg  * (cfr[nt][0] + b0v);
            oacc[nt][1] += hg  * (cfr[nt][1] + b1v);
            oacc[nt][2] += hg8 * (cfr[nt][2] + b0v);
            oacc[nt][3] += hg8 * (cfr[nt][3] + b1v);
        }
    }

    // combine the wn=0 / wn=1 partial n-sums (same rows, same cols)
    __syncthreads();
    if (wn == 1) {
#pragma unroll
        for (int nt = 0; nt < 8; nt++)
            ((float4*)&red[wm * 1024 + nt * 128 + lane * 4])[0] =
                make_float4(oacc[nt][0], oacc[nt][1], oacc[nt][2], oacc[nt][3]);
    }
    __syncthreads();
    if (wn == 0) {
#pragma unroll
        for (int nt = 0; nt < 8; nt++) {
            float4 p = ((float4*)&red[wm * 1024 + nt * 128 + lane * 4])[0];
            int d = nt * 8 + 2 * tg;
            float2 s0 = make_float2(oacc[nt][0] + p.x, oacc[nt][1] + p.y);
            float2 s1 = make_float2(oacc[nt][2] + p.z, oacc[nt][3] + p.w);
            *(float2*)&out[(size_t)(row0 + rA0) * DM + d] = s0;
            *(float2*)&out[(size_t)(row0 + rA1) * DM + d] = s1;
        }
    }
}

// ---------------------------------------------------------------------------
// Launch
// ---------------------------------------------------------------------------
extern "C" void kernel_launch(void* const* d_in, const int* in_sizes, int n_in,
                              void* d_out, int out_size)
{
    (void)in_sizes; (void)n_in; (void)out_size;
    const float* x  = (const float*)d_in[0];
    const float* WA = (const float*)d_in[1];
    const float* bA = (const float*)d_in[2];
    const float* WB = (const float*)d_in[3];
    const float* bB = (const float*)d_in[4];
    const float* WC = (const float*)d_in[5];
    const float* bC = (const float*)d_in[6];
    float* out = (float*)d_out;

    const int s1 = 24064 * 4;                 // 96,256 B
    const int s2 = (8192 + 1024 + 2*272 + 2*16) * 4;   // 39,232 B
    const int s3 = (17408 + 1024) * 4;        // 73,728 B
    const int s4 = 23888 * 4;                 // 95,552 B

    cudaFuncSetAttribute(k1_proj,         cudaFuncAttributeMaxDynamicSharedMemorySize, s1);
    cudaFuncSetAttribute(k2_chunk_prefix, cudaFuncAttributeMaxDynamicSharedMemorySize, s2);
    cudaFuncSetAttribute(k3_chunk_scan,   cudaFuncAttributeMaxDynamicSharedMemorySize, s3);
    cudaFuncSetAttribute(k4_out,          cudaFuncAttributeMaxDynamicSharedMemorySize, s4);

    k0_round       <<<144,    256>>>(WA, WB, WC);
    k1_proj        <<<NCHUNK, 256, s1>>>(x, bA, bB);
    k2_chunk_prefix<<<NCHUNK, 256, s2>>>();
    k3_chunk_scan  <<<BATCH,  256, s3>>>();
    k4_out         <<<NCHUNK, 256, s4>>>(x, bC, out);
}